// round 1
// baseline (speedup 1.0000x reference)
#include <cuda_runtime.h>
#include <cstdint>

#define BB 8
#define NN 2048
#define KK 20
#define CATC 512

// ---------------- static scratch (no allocations allowed) ----------------
__device__ float g_D[(size_t)BB * NN * NN];      // 134 MB pairwise "pd"
__device__ int   g_idx[BB * NN * KK];            // knn indices
__device__ float g_xx[BB * NN];                  // per-point squared norms
__device__ float g_cat[(size_t)BB * NN * CATC];  // concat feature buffer (B,N,512)
__device__ float g_t[(size_t)BB * NN * 256];     // center-term GEMM output (B,N,O)
__device__ float g_h5[(size_t)BB * NN * 512];    // final conv pre-norm
__device__ float g_partS[(size_t)8 * 2 * 512 * 128]; // per-block partial sums
__device__ float g_partQ[(size_t)8 * 2 * 512 * 128]; // per-block partial sumsq
__device__ float g_sum[BB * 512];
__device__ float g_sumsq[BB * 512];

// ---------------- xx: per-point squared norm ----------------
__global__ void xx_kernel(const float* __restrict__ xin, int use_in, int xoff, int C) {
    int i = blockIdx.x * blockDim.x + threadIdx.x;
    if (i >= BB * NN) return;
    const float* p = use_in ? (xin + (size_t)i * 3) : (g_cat + (size_t)i * CATC + xoff);
    float s = 0.f;
    for (int c = 0; c < C; ++c) s += p[c] * p[c];
    g_xx[i] = s;
}

// ---------------- distance GEMM: D[n][m] = 2*dot(x_n,x_m) - xx_n - xx_m ----------------
__global__ void dist_gemm(const float* __restrict__ xin, int use_in, int xoff, int C) {
    __shared__ __align__(16) float As[16][68];
    __shared__ __align__(16) float Bs[16][68];
    int b = blockIdx.z, n0 = blockIdx.y * 64, m0 = blockIdx.x * 64;
    int tid = threadIdx.x, tx = tid & 15, ty = tid >> 4;
    float acc[4][4] = {};
    int nch = (C + 15) >> 4;
    for (int ch = 0; ch < nch; ++ch) {
        int c0 = ch * 16;
        for (int t = tid; t < 2048; t += 256) {
            int which = t >> 10;
            int r = (t & 1023) >> 4;
            int cc = t & 15;
            int c = c0 + cc;
            int rowg = b * NN + (which ? m0 : n0) + r;
            float v = 0.f;
            if (c < C)
                v = use_in ? xin[(size_t)rowg * 3 + c]
                           : g_cat[(size_t)rowg * CATC + xoff + c];
            if (which) Bs[cc][r] = v; else As[cc][r] = v;
        }
        __syncthreads();
#pragma unroll
        for (int cc = 0; cc < 16; ++cc) {
            float4 a4 = *(const float4*)&As[cc][ty * 4];
            float4 b4 = *(const float4*)&Bs[cc][tx * 4];
            float aa[4] = {a4.x, a4.y, a4.z, a4.w};
            float bb[4] = {b4.x, b4.y, b4.z, b4.w};
#pragma unroll
            for (int i = 0; i < 4; ++i)
#pragma unroll
                for (int j = 0; j < 4; ++j)
                    acc[i][j] = fmaf(aa[i], bb[j], acc[i][j]);
        }
        __syncthreads();
    }
    float xn[4], xm[4];
#pragma unroll
    for (int i = 0; i < 4; ++i) xn[i] = g_xx[b * NN + n0 + ty * 4 + i];
#pragma unroll
    for (int j = 0; j < 4; ++j) xm[j] = g_xx[b * NN + m0 + tx * 4 + j];
#pragma unroll
    for (int i = 0; i < 4; ++i) {
        float4 o4;
        o4.x = 2.f * acc[i][0] - xn[i] - xm[0];
        o4.y = 2.f * acc[i][1] - xn[i] - xm[1];
        o4.z = 2.f * acc[i][2] - xn[i] - xm[2];
        o4.w = 2.f * acc[i][3] - xn[i] - xm[3];
        *(float4*)&g_D[((size_t)(b * NN + n0 + ty * 4 + i)) * NN + m0 + tx * 4] = o4;
    }
}

// ---------------- top-K=20 (argmax sweep, lowest-index tie-break like lax.top_k) ----------------
__global__ void topk_kernel() {
    __shared__ float sd[NN];
    __shared__ float rv[256];
    __shared__ int   ri[256];
    int n = blockIdx.x, b = blockIdx.y;
    int tid = threadIdx.x;
    const float* row = g_D + ((size_t)(b * NN + n)) * NN;
    for (int i = tid; i < NN; i += 256) sd[i] = row[i];
    __syncthreads();
    for (int kk = 0; kk < KK; ++kk) {
        float best = -3.402823466e38f;
        int bi = NN;
        for (int i = tid; i < NN; i += 256) {
            float v = sd[i];
            if (v > best || (v == best && i < bi)) { best = v; bi = i; }
        }
        rv[tid] = best; ri[tid] = bi;
        __syncthreads();
        for (int s = 128; s > 0; s >>= 1) {
            if (tid < s) {
                float v2 = rv[tid + s]; int i2 = ri[tid + s];
                if (v2 > rv[tid] || (v2 == rv[tid] && i2 < ri[tid])) { rv[tid] = v2; ri[tid] = i2; }
            }
            __syncthreads();
        }
        if (tid == 0) {
            g_idx[(b * NN + n) * KK + kk] = ri[0];
            sd[ri[0]] = -3.402823466e38f;
        }
        __syncthreads();
    }
}

// ---------------- center GEMM: t[row][o] = sum_c (w[o][C+c]-w[o][c]) * x[row][c] ----------------
__global__ void center_gemm(const float* __restrict__ xin, int use_in, int xoff, int C,
                            const float* __restrict__ w, int O) {
    __shared__ __align__(16) float As[16][68];
    __shared__ __align__(16) float Bs[16][68];
    int r0 = blockIdx.y * 64, o0 = blockIdx.x * 64;
    int tid = threadIdx.x, tx = tid & 15, ty = tid >> 4;
    float acc[4][4] = {};
    int twoC = 2 * C;
    int nch = (C + 15) >> 4;
    for (int ch = 0; ch < nch; ++ch) {
        int c0 = ch * 16;
        for (int t = tid; t < 2048; t += 256) {
            int which = t >> 10;
            int r = (t & 1023) >> 4;
            int cc = t & 15;
            int c = c0 + cc;
            float v = 0.f;
            if (which == 0) {
                if (c < C)
                    v = use_in ? xin[(size_t)(r0 + r) * 3 + c]
                               : g_cat[(size_t)(r0 + r) * CATC + xoff + c];
                As[cc][r] = v;
            } else {
                if (c < C && (o0 + r) < O)
                    v = w[(size_t)(o0 + r) * twoC + C + c] - w[(size_t)(o0 + r) * twoC + c];
                Bs[cc][r] = v;
            }
        }
        __syncthreads();
#pragma unroll
        for (int cc = 0; cc < 16; ++cc) {
            float4 a4 = *(const float4*)&As[cc][ty * 4];
            float4 b4 = *(const float4*)&Bs[cc][tx * 4];
            float aa[4] = {a4.x, a4.y, a4.z, a4.w};
            float bb[4] = {b4.x, b4.y, b4.z, b4.w};
#pragma unroll
            for (int i = 0; i < 4; ++i)
#pragma unroll
                for (int j = 0; j < 4; ++j)
                    acc[i][j] = fmaf(aa[i], bb[j], acc[i][j]);
        }
        __syncthreads();
    }
#pragma unroll
    for (int i = 0; i < 4; ++i) {
        float4 o4 = make_float4(acc[i][0], acc[i][1], acc[i][2], acc[i][3]);
        *(float4*)&g_t[(size_t)(r0 + ty * 4 + i) * O + o0 + tx * 4] = o4;
    }
}

// ---------------- gather GEMM + fused max/sum/sumsq epilogue ----------------
// block: 4 points x K=20 = 80 rows, 128 output channels; 256 threads, 5x8 micro-tile
__global__ void gather_gemm(const float* __restrict__ xin, int use_in, int xoff, int C,
                            const float* __restrict__ w, int O, int outoff) {
    __shared__ __align__(16) float As[80][20];
    __shared__ __align__(16) float Bs[16][132];
    __shared__ float redM[16][132];
    __shared__ float redS[16][132];
    __shared__ float redQ[16][132];
    __shared__ int sidx[80];
    int b = blockIdx.z, n0 = blockIdx.y * 4, o0 = blockIdx.x * 128;
    int tid = threadIdx.x, tx = tid & 15, ty = tid >> 4;
    if (tid < 80) sidx[tid] = g_idx[(b * NN + n0 + tid / KK) * KK + tid % KK];
    __syncthreads();
    float acc[5][8] = {};
    int twoC = 2 * C;
    int nch = (C + 15) >> 4;
    for (int ch = 0; ch < nch; ++ch) {
        int c0 = ch * 16;
        for (int t = tid; t < 320; t += 256) {
            int r = t >> 2, seg = t & 3;
            int nbr = sidx[r];
            if (use_in) {
#pragma unroll
                for (int e = 0; e < 4; ++e) {
                    int c = c0 + seg * 4 + e;
                    As[r][seg * 4 + e] = (c < C) ? xin[(size_t)(b * NN + nbr) * 3 + c] : 0.f;
                }
            } else {
                // C is a multiple of 16 here (64 or 128): full float4 in range
                float4 v = *(const float4*)&g_cat[(size_t)(b * NN + nbr) * CATC + xoff + c0 + seg * 4];
                *(float4*)&As[r][seg * 4] = v;
            }
        }
        for (int t = tid; t < 2048; t += 256) {
            int o = t >> 4, cc = t & 15;
            int c = c0 + cc;
            Bs[cc][o] = ((o0 + o) < O && c < C) ? w[(size_t)(o0 + o) * twoC + c] : 0.f;
        }
        __syncthreads();
#pragma unroll
        for (int cc = 0; cc < 16; ++cc) {
            float a0 = As[ty * 5 + 0][cc];
            float a1 = As[ty * 5 + 1][cc];
            float a2 = As[ty * 5 + 2][cc];
            float a3 = As[ty * 5 + 3][cc];
            float a4 = As[ty * 5 + 4][cc];
            float4 b0 = *(const float4*)&Bs[cc][tx * 8];
            float4 b1 = *(const float4*)&Bs[cc][tx * 8 + 4];
            float bb[8] = {b0.x, b0.y, b0.z, b0.w, b1.x, b1.y, b1.z, b1.w};
#pragma unroll
            for (int j = 0; j < 8; ++j) {
                acc[0][j] = fmaf(a0, bb[j], acc[0][j]);
                acc[1][j] = fmaf(a1, bb[j], acc[1][j]);
                acc[2][j] = fmaf(a2, bb[j], acc[2][j]);
                acc[3][j] = fmaf(a3, bb[j], acc[3][j]);
                acc[4][j] = fmaf(a4, bb[j], acc[4][j]);
            }
        }
        __syncthreads();
    }
    // epilogue: add center term, local max/sum/sumsq over this thread's 5 k-rows
    int p = ty >> 2;                 // point index within block (5 rows of one point per thread)
    int nrow = b * NN + n0 + p;
    float lmax[8], lsum[8], lssq[8];
#pragma unroll
    for (int j = 0; j < 8; ++j) {
        int o = o0 + tx * 8 + j;
        float tval = (o < O) ? g_t[(size_t)nrow * O + o] : 0.f;
        float mx = -3.402823466e38f, s = 0.f, q = 0.f;
#pragma unroll
        for (int i = 0; i < 5; ++i) {
            float h = acc[i][j] + tval;
            mx = fmaxf(mx, h);
            s += h;
            q += h * h;
        }
        lmax[j] = mx; lsum[j] = s; lssq[j] = q;
    }
#pragma unroll
    for (int j = 0; j < 8; ++j) {
        redM[ty][tx * 8 + j] = lmax[j];
        redS[ty][tx * 8 + j] = lsum[j];
        redQ[ty][tx * 8 + j] = lssq[j];
    }
    __syncthreads();
    // max over k (4 ty-groups per point), write raw max into concat slice
    for (int t = tid; t < 512; t += 256) {
        int pp = t >> 7, col = t & 127;
        float m0 = fmaxf(redM[pp * 4 + 0][col], redM[pp * 4 + 1][col]);
        float m1 = fmaxf(redM[pp * 4 + 2][col], redM[pp * 4 + 3][col]);
        if (o0 + col < O)
            g_cat[(size_t)(b * NN + n0 + pp) * CATC + outoff + o0 + col] = fmaxf(m0, m1);
    }
    // deterministic partial sums per block
    if (tid < 128) {
        float s = 0.f, q = 0.f;
#pragma unroll
        for (int yy = 0; yy < 16; ++yy) { s += redS[yy][tid]; q += redQ[yy][tid]; }
        size_t pidx = (((size_t)b * gridDim.x + blockIdx.x) * (NN / 4) + blockIdx.y) * 128 + tid;
        g_partS[pidx] = s;
        g_partQ[pidx] = q;
    }
}

// ---------------- reduce gather partials -> g_sum/g_sumsq ----------------
__global__ void reduce_conv(int O, int oT) {
    int i = blockIdx.x * 256 + threadIdx.x;
    if (i >= BB * O) return;
    int b = i / O, o = i - b * O;
    int ot = o >> 7, col = o & 127;
    float s = 0.f, q = 0.f;
    for (int ny = 0; ny < NN / 4; ++ny) {
        size_t p = (((size_t)b * oT + ot) * (NN / 4) + ny) * 128 + col;
        s += g_partS[p];
        q += g_partQ[p];
    }
    g_sum[i] = s;
    g_sumsq[i] = q;
}

// ---------------- finalize edge conv: instnorm + leaky, in place on concat slice ----------------
__global__ void finalize_conv(int O, int outoff) {
    int i = blockIdx.x * 256 + threadIdx.x;
    if (i >= BB * NN * O) return;
    int row = i / O;
    int o = i - row * O;
    int b = row >> 11;  // row / NN
    const float cnt = (float)(NN * KK);
    float mean = g_sum[b * O + o] / cnt;
    float var = fmaxf(g_sumsq[b * O + o] / cnt - mean * mean, 0.f);
    float inv = rsqrtf(var + 1e-5f);
    size_t pidx = (size_t)row * CATC + outoff + o;
    float v = (g_cat[pidx] - mean) * inv;
    g_cat[pidx] = v >= 0.f ? v : 0.2f * v;
}

// ---------------- final conv GEMM (512x512) with fused sum/sumsq partials ----------------
__global__ void final_gemm(const float* __restrict__ w5) {
    __shared__ __align__(16) float As[16][68];
    __shared__ __align__(16) float Bs[16][68];
    __shared__ float redS[16][64];
    __shared__ float redQ[16][64];
    int r0 = blockIdx.y * 64, o0 = blockIdx.x * 64;
    int tid = threadIdx.x, tx = tid & 15, ty = tid >> 4;
    float acc[4][4] = {};
    for (int ch = 0; ch < 32; ++ch) {
        int c0 = ch * 16;
        for (int t = tid; t < 2048; t += 256) {
            int which = t >> 10;
            int r = (t & 1023) >> 4;
            int cc = t & 15;
            float v;
            if (which == 0) {
                v = g_cat[(size_t)(r0 + r) * CATC + c0 + cc];
                As[cc][r] = v;
            } else {
                v = w5[(size_t)(o0 + r) * 512 + c0 + cc];
                Bs[cc][r] = v;
            }
        }
        __syncthreads();
#pragma unroll
        for (int cc = 0; cc < 16; ++cc) {
            float4 a4 = *(const float4*)&As[cc][ty * 4];
            float4 b4 = *(const float4*)&Bs[cc][tx * 4];
            float aa[4] = {a4.x, a4.y, a4.z, a4.w};
            float bb[4] = {b4.x, b4.y, b4.z, b4.w};
#pragma unroll
            for (int i = 0; i < 4; ++i)
#pragma unroll
                for (int j = 0; j < 4; ++j)
                    acc[i][j] = fmaf(aa[i], bb[j], acc[i][j]);
        }
        __syncthreads();
    }
    float ls[4] = {0, 0, 0, 0}, lq[4] = {0, 0, 0, 0};
#pragma unroll
    for (int i = 0; i < 4; ++i) {
        float4 o4 = make_float4(acc[i][0], acc[i][1], acc[i][2], acc[i][3]);
        *(float4*)&g_h5[(size_t)(r0 + ty * 4 + i) * 512 + o0 + tx * 4] = o4;
#pragma unroll
        for (int j = 0; j < 4; ++j) { ls[j] += acc[i][j]; lq[j] += acc[i][j] * acc[i][j]; }
    }
#pragma unroll
    for (int j = 0; j < 4; ++j) { redS[ty][tx * 4 + j] = ls[j]; redQ[ty][tx * 4 + j] = lq[j]; }
    __syncthreads();
    if (tid < 64) {
        float s = 0.f, q = 0.f;
#pragma unroll
        for (int yy = 0; yy < 16; ++yy) { s += redS[yy][tid]; q += redQ[yy][tid]; }
        size_t p = ((size_t)blockIdx.y * 8 + blockIdx.x) * 64 + tid;
        g_partS[p] = s;
        g_partQ[p] = q;
    }
}

__global__ void reduce_final() {
    int i = blockIdx.x * 256 + threadIdx.x;
    if (i >= BB * 512) return;
    int b = i >> 9, o = i & 511;
    int ox = o >> 6, col = o & 63;
    float s = 0.f, q = 0.f;
    for (int yy = 0; yy < 32; ++yy) {
        size_t p = ((size_t)(b * 32 + yy) * 8 + ox) * 64 + col;
        s += g_partS[p];
        q += g_partQ[p];
    }
    g_sum[i] = s;
    g_sumsq[i] = q;
}

// ---------------- final normalize + leaky + transpose to (B,512,N) ----------------
__global__ void finalize_final(float* __restrict__ out) {
    int n = blockIdx.x * blockDim.x + threadIdx.x;
    int o = blockIdx.y, b = blockIdx.z;
    const float cnt = (float)NN;
    float mean = g_sum[b * 512 + o] / cnt;
    float var = fmaxf(g_sumsq[b * 512 + o] / cnt - mean * mean, 0.f);
    float inv = rsqrtf(var + 1e-5f);
    float v = (g_h5[(size_t)(b * NN + n) * 512 + o] - mean) * inv;
    out[((size_t)b * 512 + o) * NN + n] = v >= 0.f ? v : 0.2f * v;
}

// ---------------- host orchestration ----------------
static void run_edge(const float* xin, int use_in, int xoff, int C,
                     const float* w, int O, int outoff) {
    xx_kernel<<<(BB * NN + 255) / 256, 256>>>(xin, use_in, xoff, C);
    dist_gemm<<<dim3(NN / 64, NN / 64, BB), 256>>>(xin, use_in, xoff, C);
    topk_kernel<<<dim3(NN, BB), 256>>>();
    center_gemm<<<dim3((O + 63) / 64, (BB * NN) / 64), 256>>>(xin, use_in, xoff, C, w, O);
    int oT = (O + 127) / 128;
    gather_gemm<<<dim3(oT, NN / 4, BB), 256>>>(xin, use_in, xoff, C, w, O, outoff);
    reduce_conv<<<(BB * O + 255) / 256, 256>>>(O, oT);
    finalize_conv<<<(BB * NN * O + 255) / 256, 256>>>(O, outoff);
}

extern "C" void kernel_launch(void* const* d_in, const int* in_sizes, int n_in,
                              void* d_out, int out_size) {
    const float* x  = (const float*)d_in[0];
    const float* w1 = (const float*)d_in[1];
    const float* w2 = (const float*)d_in[2];
    const float* w3 = (const float*)d_in[3];
    const float* w4 = (const float*)d_in[4];
    const float* w5 = (const float*)d_in[5];
    float* out = (float*)d_out;

    run_edge(x, 1, 0,   3,   w1, 64,  0);    // x1 -> cat[:, :,   0: 64]
    run_edge(x, 0, 0,   64,  w2, 64,  64);   // x2 -> cat[:, :,  64:128]
    run_edge(x, 0, 64,  64,  w3, 128, 128);  // x3 -> cat[:, :, 128:256]
    run_edge(x, 0, 128, 128, w4, 256, 256);  // x4 -> cat[:, :, 256:512]

    final_gemm<<<dim3(512 / 64, (BB * NN) / 64), 256>>>(w5);
    reduce_final<<<(BB * 512 + 255) / 256, 256>>>();
    finalize_final<<<dim3(NN / 256, 512, BB), 256>>>(out);
}

// round 3
// speedup vs baseline: 1.3087x; 1.3087x over previous
#include <cuda_runtime.h>
#include <cstdint>

#define BB 8
#define NN 2048
#define KK 20
#define CATC 512

// ---------------- static scratch (no allocations allowed) ----------------
__device__ float g_D[(size_t)BB * NN * NN];      // 134 MB pairwise "pd"
__device__ int   g_idx[BB * NN * KK];            // knn indices
__device__ float g_xx[BB * NN];                  // per-point squared norms
__device__ float g_cat[(size_t)BB * NN * CATC];  // concat feature buffer (B,N,512)
__device__ float g_t[(size_t)BB * NN * 256];     // center-term GEMM output (B,N,O)
__device__ float g_h5[(size_t)BB * NN * 512];    // final conv pre-norm
__device__ float g_partS[(size_t)8 * 2 * 512 * 128]; // per-block partial sums
__device__ float g_partQ[(size_t)8 * 2 * 512 * 128]; // per-block partial sumsq
__device__ float g_sum[BB * 512];
__device__ float g_sumsq[BB * 512];

// ---------------- xx: per-point squared norm ----------------
__global__ void xx_kernel(const float* __restrict__ xin, int use_in, int xoff, int C) {
    int i = blockIdx.x * blockDim.x + threadIdx.x;
    if (i >= BB * NN) return;
    const float* p = use_in ? (xin + (size_t)i * 3) : (g_cat + (size_t)i * CATC + xoff);
    float s = 0.f;
    for (int c = 0; c < C; ++c) s += p[c] * p[c];
    g_xx[i] = s;
}

// ---------------- distance GEMM: D[n][m] = 2*dot(x_n,x_m) - xx_n - xx_m ----------------
__global__ void dist_gemm(const float* __restrict__ xin, int use_in, int xoff, int C) {
    __shared__ __align__(16) float As[16][68];
    __shared__ __align__(16) float Bs[16][68];
    int b = blockIdx.z, n0 = blockIdx.y * 64, m0 = blockIdx.x * 64;
    int tid = threadIdx.x, tx = tid & 15, ty = tid >> 4;
    float acc[4][4] = {};
    int nch = (C + 15) >> 4;
    for (int ch = 0; ch < nch; ++ch) {
        int c0 = ch * 16;
        for (int t = tid; t < 2048; t += 256) {
            int which = t >> 10;
            int r = (t & 1023) >> 4;
            int cc = t & 15;
            int c = c0 + cc;
            int rowg = b * NN + (which ? m0 : n0) + r;
            float v = 0.f;
            if (c < C)
                v = use_in ? xin[(size_t)rowg * 3 + c]
                           : g_cat[(size_t)rowg * CATC + xoff + c];
            if (which) Bs[cc][r] = v; else As[cc][r] = v;
        }
        __syncthreads();
#pragma unroll
        for (int cc = 0; cc < 16; ++cc) {
            float4 a4 = *(const float4*)&As[cc][ty * 4];
            float4 b4 = *(const float4*)&Bs[cc][tx * 4];
            float aa[4] = {a4.x, a4.y, a4.z, a4.w};
            float bb[4] = {b4.x, b4.y, b4.z, b4.w};
#pragma unroll
            for (int i = 0; i < 4; ++i)
#pragma unroll
                for (int j = 0; j < 4; ++j)
                    acc[i][j] = fmaf(aa[i], bb[j], acc[i][j]);
        }
        __syncthreads();
    }
    float xn[4], xm[4];
#pragma unroll
    for (int i = 0; i < 4; ++i) xn[i] = g_xx[b * NN + n0 + ty * 4 + i];
#pragma unroll
    for (int j = 0; j < 4; ++j) xm[j] = g_xx[b * NN + m0 + tx * 4 + j];
#pragma unroll
    for (int i = 0; i < 4; ++i) {
        float4 o4;
        o4.x = 2.f * acc[i][0] - xn[i] - xm[0];
        o4.y = 2.f * acc[i][1] - xn[i] - xm[1];
        o4.z = 2.f * acc[i][2] - xn[i] - xm[2];
        o4.w = 2.f * acc[i][3] - xn[i] - xm[3];
        *(float4*)&g_D[((size_t)(b * NN + n0 + ty * 4 + i)) * NN + m0 + tx * 4] = o4;
    }
}

// ---------------- top-K=20 via exact 4-pass radix select ----------------
// Emits indices in EXACTLY the order of 20x iterative argmax with lowest-index
// tie-break (value desc, ties index asc) so g_idx is bit-identical to that scheme.
__global__ void topk_kernel() {
    __shared__ unsigned keys[NN];
    __shared__ int      eq[NN];
    __shared__ unsigned hist[256];
    __shared__ unsigned suf[256];
    __shared__ int      rmin[256];
    __shared__ unsigned selK[24];
    __shared__ int      selI[24];
    __shared__ unsigned s_prefix;
    __shared__ int      s_remaining, s_selt, s_cntgt, s_cnteq;

    int n = blockIdx.x, b = blockIdx.y;
    int tid = threadIdx.x;
    size_t rowbase = (size_t)(b * NN + n);
    const float4* row4 = (const float4*)(g_D + rowbase * NN);

    // load row, convert to order-preserving uint keys
    for (int i = tid; i < NN / 4; i += 256) {
        float4 v = row4[i];
        float vv[4] = {v.x, v.y, v.z, v.w};
#pragma unroll
        for (int e = 0; e < 4; ++e) {
            unsigned u = __float_as_uint(vv[e]);
            keys[i * 4 + e] = (u & 0x80000000u) ? ~u : (u | 0x80000000u);
        }
    }
    if (tid == 0) { s_prefix = 0u; s_remaining = KK; }
    __syncthreads();

#pragma unroll
    for (int p = 0; p < 4; ++p) {
        hist[tid] = 0u;
        __syncthreads();
        unsigned pref = s_prefix;
        int rem = s_remaining;
        const int shift = 24 - 8 * p;
        for (int i = tid; i < NN; i += 256) {
            unsigned k = keys[i];
            bool act = (p == 0) || ((k >> (shift + 8)) == pref);
            if (act) atomicAdd(&hist[(k >> shift) & 0xFFu], 1u);
        }
        __syncthreads();
        // suffix sums: suf[i] = sum hist[i..255]
        suf[tid] = hist[tid];
        __syncthreads();
#pragma unroll
        for (int d = 1; d < 256; d <<= 1) {
            unsigned v = (tid + d < 256) ? suf[tid + d] : 0u;
            __syncthreads();
            suf[tid] += v;
            __syncthreads();
        }
        if (suf[tid] >= (unsigned)rem && (tid == 255 || suf[tid + 1] < (unsigned)rem))
            s_selt = tid;
        __syncthreads();
        if (tid == 0) {
            int t = s_selt;
            unsigned above = (t == 255) ? 0u : suf[t + 1];
            s_remaining = rem - (int)above;
            s_prefix = (pref << 8) | (unsigned)t;
        }
        __syncthreads();
    }

    unsigned T = s_prefix;      // exact key of the 20th-largest value
    int r = s_remaining;        // how many ==T entries to take (lowest indices)
    if (tid == 0) { s_cntgt = 0; s_cnteq = 0; }
    __syncthreads();
    int* outp = g_idx + rowbase * KK;
    for (int i = tid; i < NN; i += 256) {
        unsigned k = keys[i];
        if (k > T) {
            int pos = atomicAdd(&s_cntgt, 1);
            selK[pos] = k;
            selI[pos] = i;
        } else if (k == T) {
            int pos = atomicAdd(&s_cnteq, 1);
            eq[pos] = i;
        }
    }
    __syncthreads();
    int m = s_cntgt;            // == KK - r by construction (m <= 19)
    int L = s_cnteq;
    // thread 0: insertion-sort the >T entries by (key desc, index asc), emit first
    if (tid == 0) {
        for (int a = 1; a < m; ++a) {
            unsigned kk = selK[a]; int ii = selI[a];
            int bp = a - 1;
            while (bp >= 0 && (selK[bp] < kk || (selK[bp] == kk && selI[bp] > ii))) {
                selK[bp + 1] = selK[bp]; selI[bp + 1] = selI[bp]; --bp;
            }
            selK[bp + 1] = kk; selI[bp + 1] = ii;
        }
        for (int a = 0; a < m; ++a) outp[a] = selI[a];
    }
    __syncthreads();
    // boundary (==T) entries: emit the r smallest indices in ascending order
    for (int round = 0; round < r; ++round) {
        int lm = 0x7FFFFFFF;
        for (int i = tid; i < L; i += 256) lm = min(lm, eq[i]);
        rmin[tid] = lm;
        __syncthreads();
#pragma unroll
        for (int s = 128; s > 0; s >>= 1) {
            if (tid < s) rmin[tid] = min(rmin[tid], rmin[tid + s]);
            __syncthreads();
        }
        int mv = rmin[0];
        if (tid == 0) outp[m + round] = mv;
        for (int i = tid; i < L; i += 256)
            if (eq[i] == mv) eq[i] = 0x7FFFFFFF;
        __syncthreads();
    }
}

// ---------------- center GEMM: t[row][o] = sum_c (w[o][C+c]-w[o][c]) * x[row][c] ----------------
__global__ void center_gemm(const float* __restrict__ xin, int use_in, int xoff, int C,
                            const float* __restrict__ w, int O) {
    __shared__ __align__(16) float As[16][68];
    __shared__ __align__(16) float Bs[16][68];
    int r0 = blockIdx.y * 64, o0 = blockIdx.x * 64;
    int tid = threadIdx.x, tx = tid & 15, ty = tid >> 4;
    float acc[4][4] = {};
    int twoC = 2 * C;
    int nch = (C + 15) >> 4;
    for (int ch = 0; ch < nch; ++ch) {
        int c0 = ch * 16;
        for (int t = tid; t < 2048; t += 256) {
            int which = t >> 10;
            int r = (t & 1023) >> 4;
            int cc = t & 15;
            int c = c0 + cc;
            float v = 0.f;
            if (which == 0) {
                if (c < C)
                    v = use_in ? xin[(size_t)(r0 + r) * 3 + c]
                               : g_cat[(size_t)(r0 + r) * CATC + xoff + c];
                As[cc][r] = v;
            } else {
                if (c < C && (o0 + r) < O)
                    v = w[(size_t)(o0 + r) * twoC + C + c] - w[(size_t)(o0 + r) * twoC + c];
                Bs[cc][r] = v;
            }
        }
        __syncthreads();
#pragma unroll
        for (int cc = 0; cc < 16; ++cc) {
            float4 a4 = *(const float4*)&As[cc][ty * 4];
            float4 b4 = *(const float4*)&Bs[cc][tx * 4];
            float aa[4] = {a4.x, a4.y, a4.z, a4.w};
            float bb[4] = {b4.x, b4.y, b4.z, b4.w};
#pragma unroll
            for (int i = 0; i < 4; ++i)
#pragma unroll
                for (int j = 0; j < 4; ++j)
                    acc[i][j] = fmaf(aa[i], bb[j], acc[i][j]);
        }
        __syncthreads();
    }
#pragma unroll
    for (int i = 0; i < 4; ++i) {
        float4 o4 = make_float4(acc[i][0], acc[i][1], acc[i][2], acc[i][3]);
        *(float4*)&g_t[(size_t)(r0 + ty * 4 + i) * O + o0 + tx * 4] = o4;
    }
}

// ---------------- gather GEMM + fused max/sum/sumsq epilogue ----------------
// block: 4 points x K=20 = 80 rows, 128 output channels; 256 threads, 5x8 micro-tile
__global__ void gather_gemm(const float* __restrict__ xin, int use_in, int xoff, int C,
                            const float* __restrict__ w, int O, int outoff) {
    __shared__ __align__(16) float As[80][20];
    __shared__ __align__(16) float Bs[16][132];
    __shared__ float redM[16][132];
    __shared__ float redS[16][132];
    __shared__ float redQ[16][132];
    __shared__ int sidx[80];
    int b = blockIdx.z, n0 = blockIdx.y * 4, o0 = blockIdx.x * 128;
    int tid = threadIdx.x, tx = tid & 15, ty = tid >> 4;
    if (tid < 80) sidx[tid] = g_idx[(b * NN + n0 + tid / KK) * KK + tid % KK];
    __syncthreads();
    float acc[5][8] = {};
    int twoC = 2 * C;
    int nch = (C + 15) >> 4;
    for (int ch = 0; ch < nch; ++ch) {
        int c0 = ch * 16;
        for (int t = tid; t < 320; t += 256) {
            int r = t >> 2, seg = t & 3;
            int nbr = sidx[r];
            if (use_in) {
#pragma unroll
                for (int e = 0; e < 4; ++e) {
                    int c = c0 + seg * 4 + e;
                    As[r][seg * 4 + e] = (c < C) ? xin[(size_t)(b * NN + nbr) * 3 + c] : 0.f;
                }
            } else {
                float4 v = *(const float4*)&g_cat[(size_t)(b * NN + nbr) * CATC + xoff + c0 + seg * 4];
                *(float4*)&As[r][seg * 4] = v;
            }
        }
        for (int t = tid; t < 2048; t += 256) {
            int o = t >> 4, cc = t & 15;
            int c = c0 + cc;
            Bs[cc][o] = ((o0 + o) < O && c < C) ? w[(size_t)(o0 + o) * twoC + c] : 0.f;
        }
        __syncthreads();
#pragma unroll
        for (int cc = 0; cc < 16; ++cc) {
            float a0 = As[ty * 5 + 0][cc];
            float a1 = As[ty * 5 + 1][cc];
            float a2 = As[ty * 5 + 2][cc];
            float a3 = As[ty * 5 + 3][cc];
            float a4 = As[ty * 5 + 4][cc];
            float4 b0 = *(const float4*)&Bs[cc][tx * 8];
            float4 b1 = *(const float4*)&Bs[cc][tx * 8 + 4];
            float bb[8] = {b0.x, b0.y, b0.z, b0.w, b1.x, b1.y, b1.z, b1.w};
#pragma unroll
            for (int j = 0; j < 8; ++j) {
                acc[0][j] = fmaf(a0, bb[j], acc[0][j]);
                acc[1][j] = fmaf(a1, bb[j], acc[1][j]);
                acc[2][j] = fmaf(a2, bb[j], acc[2][j]);
                acc[3][j] = fmaf(a3, bb[j], acc[3][j]);
                acc[4][j] = fmaf(a4, bb[j], acc[4][j]);
            }
        }
        __syncthreads();
    }
    int p = ty >> 2;
    int nrow = b * NN + n0 + p;
    float lmax[8], lsum[8], lssq[8];
#pragma unroll
    for (int j = 0; j < 8; ++j) {
        int o = o0 + tx * 8 + j;
        float tval = (o < O) ? g_t[(size_t)nrow * O + o] : 0.f;
        float mx = -3.402823466e38f, s = 0.f, q = 0.f;
#pragma unroll
        for (int i = 0; i < 5; ++i) {
            float h = acc[i][j] + tval;
            mx = fmaxf(mx, h);
            s += h;
            q += h * h;
        }
        lmax[j] = mx; lsum[j] = s; lssq[j] = q;
    }
#pragma unroll
    for (int j = 0; j < 8; ++j) {
        redM[ty][tx * 8 + j] = lmax[j];
        redS[ty][tx * 8 + j] = lsum[j];
        redQ[ty][tx * 8 + j] = lssq[j];
    }
    __syncthreads();
    for (int t = tid; t < 512; t += 256) {
        int pp = t >> 7, col = t & 127;
        float m0 = fmaxf(redM[pp * 4 + 0][col], redM[pp * 4 + 1][col]);
        float m1 = fmaxf(redM[pp * 4 + 2][col], redM[pp * 4 + 3][col]);
        if (o0 + col < O)
            g_cat[(size_t)(b * NN + n0 + pp) * CATC + outoff + o0 + col] = fmaxf(m0, m1);
    }
    if (tid < 128) {
        float s = 0.f, q = 0.f;
#pragma unroll
        for (int yy = 0; yy < 16; ++yy) { s += redS[yy][tid]; q += redQ[yy][tid]; }
        size_t pidx = (((size_t)b * gridDim.x + blockIdx.x) * (NN / 4) + blockIdx.y) * 128 + tid;
        g_partS[pidx] = s;
        g_partQ[pidx] = q;
    }
}

// ---------------- reduce gather partials -> g_sum/g_sumsq ----------------
__global__ void reduce_conv(int O, int oT) {
    int i = blockIdx.x * 256 + threadIdx.x;
    if (i >= BB * O) return;
    int b = i / O, o = i - b * O;
    int ot = o >> 7, col = o & 127;
    float s = 0.f, q = 0.f;
    for (int ny = 0; ny < NN / 4; ++ny) {
        size_t p = (((size_t)b * oT + ot) * (NN / 4) + ny) * 128 + col;
        s += g_partS[p];
        q += g_partQ[p];
    }
    g_sum[i] = s;
    g_sumsq[i] = q;
}

// ---------------- finalize edge conv: instnorm + leaky, in place on concat slice ----------------
__global__ void finalize_conv(int O, int outoff) {
    int i = blockIdx.x * 256 + threadIdx.x;
    if (i >= BB * NN * O) return;
    int row = i / O;
    int o = i - row * O;
    int b = row >> 11;
    const float cnt = (float)(NN * KK);
    float mean = g_sum[b * O + o] / cnt;
    float var = fmaxf(g_sumsq[b * O + o] / cnt - mean * mean, 0.f);
    float inv = rsqrtf(var + 1e-5f);
    size_t pidx = (size_t)row * CATC + outoff + o;
    float v = (g_cat[pidx] - mean) * inv;
    g_cat[pidx] = v >= 0.f ? v : 0.2f * v;
}

// ---------------- final conv GEMM (512x512) with fused sum/sumsq partials ----------------
__global__ void final_gemm(const float* __restrict__ w5) {
    __shared__ __align__(16) float As[16][68];
    __shared__ __align__(16) float Bs[16][68];
    __shared__ float redS[16][64];
    __shared__ float redQ[16][64];
    int r0 = blockIdx.y * 64, o0 = blockIdx.x * 64;
    int tid = threadIdx.x, tx = tid & 15, ty = tid >> 4;
    float acc[4][4] = {};
    for (int ch = 0; ch < 32; ++ch) {
        int c0 = ch * 16;
        for (int t = tid; t < 2048; t += 256) {
            int which = t >> 10;
            int r = (t & 1023) >> 4;
            int cc = t & 15;
            float v;
            if (which == 0) {
                v = g_cat[(size_t)(r0 + r) * CATC + c0 + cc];
                As[cc][r] = v;
            } else {
                v = w5[(size_t)(o0 + r) * 512 + c0 + cc];
                Bs[cc][r] = v;
            }
        }
        __syncthreads();
#pragma unroll
        for (int cc = 0; cc < 16; ++cc) {
            float4 a4 = *(const float4*)&As[cc][ty * 4];
            float4 b4 = *(const float4*)&Bs[cc][tx * 4];
            float aa[4] = {a4.x, a4.y, a4.z, a4.w};
            float bb[4] = {b4.x, b4.y, b4.z, b4.w};
#pragma unroll
            for (int i = 0; i < 4; ++i)
#pragma unroll
                for (int j = 0; j < 4; ++j)
                    acc[i][j] = fmaf(aa[i], bb[j], acc[i][j]);
        }
        __syncthreads();
    }
    float ls[4] = {0, 0, 0, 0}, lq[4] = {0, 0, 0, 0};
#pragma unroll
    for (int i = 0; i < 4; ++i) {
        float4 o4 = make_float4(acc[i][0], acc[i][1], acc[i][2], acc[i][3]);
        *(float4*)&g_h5[(size_t)(r0 + ty * 4 + i) * 512 + o0 + tx * 4] = o4;
#pragma unroll
        for (int j = 0; j < 4; ++j) { ls[j] += acc[i][j]; lq[j] += acc[i][j] * acc[i][j]; }
    }
#pragma unroll
    for (int j = 0; j < 4; ++j) { redS[ty][tx * 4 + j] = ls[j]; redQ[ty][tx * 4 + j] = lq[j]; }
    __syncthreads();
    if (tid < 64) {
        float s = 0.f, q = 0.f;
#pragma unroll
        for (int yy = 0; yy < 16; ++yy) { s += redS[yy][tid]; q += redQ[yy][tid]; }
        size_t p = ((size_t)blockIdx.y * 8 + blockIdx.x) * 64 + tid;
        g_partS[p] = s;
        g_partQ[p] = q;
    }
}

__global__ void reduce_final() {
    int i = blockIdx.x * 256 + threadIdx.x;
    if (i >= BB * 512) return;
    int b = i >> 9, o = i & 511;
    int ox = o >> 6, col = o & 63;
    float s = 0.f, q = 0.f;
    for (int yy = 0; yy < 32; ++yy) {
        size_t p = ((size_t)(b * 32 + yy) * 8 + ox) * 64 + col;
        s += g_partS[p];
        q += g_partQ[p];
    }
    g_sum[i] = s;
    g_sumsq[i] = q;
}

// ---------------- final normalize + leaky + transpose to (B,512,N) ----------------
__global__ void finalize_final(float* __restrict__ out) {
    int n = blockIdx.x * blockDim.x + threadIdx.x;
    int o = blockIdx.y, b = blockIdx.z;
    const float cnt = (float)NN;
    float mean = g_sum[b * 512 + o] / cnt;
    float var = fmaxf(g_sumsq[b * 512 + o] / cnt - mean * mean, 0.f);
    float inv = rsqrtf(var + 1e-5f);
    float v = (g_h5[(size_t)(b * NN + n) * 512 + o] - mean) * inv;
    out[((size_t)b * 512 + o) * NN + n] = v >= 0.f ? v : 0.2f * v;
}

// ---------------- host orchestration ----------------
static void run_edge(const float* xin, int use_in, int xoff, int C,
                     const float* w, int O, int outoff) {
    xx_kernel<<<(BB * NN + 255) / 256, 256>>>(xin, use_in, xoff, C);
    dist_gemm<<<dim3(NN / 64, NN / 64, BB), 256>>>(xin, use_in, xoff, C);
    topk_kernel<<<dim3(NN, BB), 256>>>();
    center_gemm<<<dim3((O + 63) / 64, (BB * NN) / 64), 256>>>(xin, use_in, xoff, C, w, O);
    int oT = (O + 127) / 128;
    gather_gemm<<<dim3(oT, NN / 4, BB), 256>>>(xin, use_in, xoff, C, w, O, outoff);
    reduce_conv<<<(BB * O + 255) / 256, 256>>>(O, oT);
    finalize_conv<<<(BB * NN * O + 255) / 256, 256>>>(O, outoff);
}

extern "C" void kernel_launch(void* const* d_in, const int* in_sizes, int n_in,
                              void* d_out, int out_size) {
    const float* x  = (const float*)d_in[0];
    const float* w1 = (const float*)d_in[1];
    const float* w2 = (const float*)d_in[2];
    const float* w3 = (const float*)d_in[3];
    const float* w4 = (const float*)d_in[4];
    const float* w5 = (const float*)d_in[5];
    float* out = (float*)d_out;

    run_edge(x, 1, 0,   3,   w1, 64,  0);    // x1 -> cat[:, :,   0: 64]
    run_edge(x, 0, 0,   64,  w2, 64,  64);   // x2 -> cat[:, :,  64:128]
    run_edge(x, 0, 64,  64,  w3, 128, 128);  // x3 -> cat[:, :, 128:256]
    run_edge(x, 0, 128, 128, w4, 256, 256);  // x4 -> cat[:, :, 256:512]

    final_gemm<<<dim3(512 / 64, (BB * NN) / 64), 256>>>(w5);
    reduce_final<<<(BB * 512 + 255) / 256, 256>>>();
    finalize_final<<<dim3(NN / 256, 512, BB), 256>>>(out);
}

// round 4
// speedup vs baseline: 1.3725x; 1.0487x over previous
#include <cuda_runtime.h>
#include <cstdint>

#define BB 8
#define NN 2048
#define KK 20
#define CATC 512

// ---------------- static scratch (no allocations allowed) ----------------
__device__ float g_D[(size_t)BB * NN * NN];      // 134 MB pairwise "pd"
__device__ int   g_idx[BB * NN * KK];            // knn indices
__device__ float g_xx[BB * NN];                  // per-point squared norms
__device__ float g_cat[(size_t)BB * NN * CATC];  // concat feature buffer (B,N,512)
__device__ float g_t[(size_t)BB * NN * 256];     // center-term GEMM output (B,N,O)
__device__ float g_h5[(size_t)BB * NN * 512];    // final conv pre-norm
__device__ float g_partS[(size_t)8 * 2 * 512 * 128]; // per-block partial sums
__device__ float g_partQ[(size_t)8 * 2 * 512 * 128]; // per-block partial sumsq
__device__ float g_sum[BB * 512];
__device__ float g_sumsq[BB * 512];

// ---------------- xx: per-point squared norm ----------------
__global__ void xx_kernel(const float* __restrict__ xin, int use_in, int xoff, int C) {
    int i = blockIdx.x * blockDim.x + threadIdx.x;
    if (i >= BB * NN) return;
    const float* p = use_in ? (xin + (size_t)i * 3) : (g_cat + (size_t)i * CATC + xoff);
    float s = 0.f;
    for (int c = 0; c < C; ++c) s += p[c] * p[c];
    g_xx[i] = s;
}

// ---------------- distance GEMM (block-triangular + mirror) ----------------
// D[n][m] = 2*dot(x_n,x_m) - xx_n - xx_m, evaluated left-to-right exactly as
// (2a - xx_row) - xx_col for BOTH the direct and the mirrored element.
// 128x128 tile, 8x8 micro-tile, 256 threads. Per-output c-accumulation order
// is sequential over chunks of 16 (identical to previous version -> bit-exact).
__global__ void dist_gemm(const float* __restrict__ xin, int use_in, int xoff, int C) {
    __shared__ __align__(16) float As[16][132];
    __shared__ __align__(16) float Bs[16][132];
    int b = blockIdx.z;
    int t = blockIdx.x;
    int bi = 0;
    while (t >= 16 - bi) { t -= 16 - bi; ++bi; }
    int bj = bi + t;
    int n0 = bi * 128, m0 = bj * 128;
    int tid = threadIdx.x, tx = tid & 15, ty = tid >> 4;
    float acc[8][8] = {};
    int nch = (C + 15) >> 4;
    for (int ch = 0; ch < nch; ++ch) {
        int c0 = ch * 16;
        for (int q = tid; q < 4096; q += 256) {
            int which = q >> 11;
            int r = (q & 2047) >> 4;
            int cc = q & 15;
            int c = c0 + cc;
            int rowg = b * NN + (which ? m0 : n0) + r;
            float v = 0.f;
            if (c < C)
                v = use_in ? xin[(size_t)rowg * 3 + c]
                           : g_cat[(size_t)rowg * CATC + xoff + c];
            if (which) Bs[cc][r] = v; else As[cc][r] = v;
        }
        __syncthreads();
#pragma unroll
        for (int cc = 0; cc < 16; ++cc) {
            float4 a0 = *(const float4*)&As[cc][ty * 8];
            float4 a1 = *(const float4*)&As[cc][ty * 8 + 4];
            float4 b0 = *(const float4*)&Bs[cc][tx * 8];
            float4 b1 = *(const float4*)&Bs[cc][tx * 8 + 4];
            float aa[8] = {a0.x, a0.y, a0.z, a0.w, a1.x, a1.y, a1.z, a1.w};
            float bb[8] = {b0.x, b0.y, b0.z, b0.w, b1.x, b1.y, b1.z, b1.w};
#pragma unroll
            for (int i = 0; i < 8; ++i)
#pragma unroll
                for (int j = 0; j < 8; ++j)
                    acc[i][j] = fmaf(aa[i], bb[j], acc[i][j]);
        }
        __syncthreads();
    }
    float xn[8], xm[8];
#pragma unroll
    for (int i = 0; i < 8; ++i) xn[i] = g_xx[b * NN + n0 + ty * 8 + i];
#pragma unroll
    for (int j = 0; j < 8; ++j) xm[j] = g_xx[b * NN + m0 + tx * 8 + j];
    // direct writes: rows n-side, cols m-side
#pragma unroll
    for (int i = 0; i < 8; ++i) {
        float o[8];
#pragma unroll
        for (int j = 0; j < 8; ++j) o[j] = 2.f * acc[i][j] - xn[i] - xm[j];
        size_t base = ((size_t)(b * NN + n0 + ty * 8 + i)) * NN + m0 + tx * 8;
        *(float4*)&g_D[base] = make_float4(o[0], o[1], o[2], o[3]);
        *(float4*)&g_D[base + 4] = make_float4(o[4], o[5], o[6], o[7]);
    }
    if (bi != bj) {
        // mirror: stage transposed tile in smem (reuse As), write coalesced.
        float (*Ts)[132] = As;
#pragma unroll
        for (int g = 0; g < 8; ++g) {
            if ((tx >> 1) == g) {
#pragma unroll
                for (int j = 0; j < 8; ++j)
#pragma unroll
                    for (int i = 0; i < 8; ++i)
                        Ts[(tx & 1) * 8 + j][ty * 8 + i] = 2.f * acc[i][j] - xm[j] - xn[i];
            }
            __syncthreads();
            for (int q = tid; q < 512; q += 256) {
                int lr = q >> 5;
                int fc = (q & 31) * 4;
                size_t base = ((size_t)(b * NN + m0 + g * 16 + lr)) * NN + n0 + fc;
                *(float4*)&g_D[base] = *(const float4*)&Ts[lr][fc];
            }
            __syncthreads();
        }
    }
}

// ---------------- top-K=20 via exact 4-pass radix select ----------------
// Emits indices in EXACTLY the order of 20x iterative argmax with lowest-index
// tie-break (value desc, ties index asc) so g_idx is bit-identical to that scheme.
__global__ void topk_kernel() {
    __shared__ unsigned keys[NN];
    __shared__ int      eq[NN];
    __shared__ unsigned hist[256];
    __shared__ unsigned suf[256];
    __shared__ int      rmin[256];
    __shared__ unsigned selK[24];
    __shared__ int      selI[24];
    __shared__ unsigned s_prefix;
    __shared__ int      s_remaining, s_selt, s_cntgt, s_cnteq;

    int n = blockIdx.x, b = blockIdx.y;
    int tid = threadIdx.x;
    size_t rowbase = (size_t)(b * NN + n);
    const float4* row4 = (const float4*)(g_D + rowbase * NN);

    for (int i = tid; i < NN / 4; i += 256) {
        float4 v = row4[i];
        float vv[4] = {v.x, v.y, v.z, v.w};
#pragma unroll
        for (int e = 0; e < 4; ++e) {
            unsigned u = __float_as_uint(vv[e]);
            keys[i * 4 + e] = (u & 0x80000000u) ? ~u : (u | 0x80000000u);
        }
    }
    if (tid == 0) { s_prefix = 0u; s_remaining = KK; }
    __syncthreads();

#pragma unroll
    for (int p = 0; p < 4; ++p) {
        hist[tid] = 0u;
        __syncthreads();
        unsigned pref = s_prefix;
        int rem = s_remaining;
        const int shift = 24 - 8 * p;
        for (int i = tid; i < NN; i += 256) {
            unsigned k = keys[i];
            bool act = (p == 0) || ((k >> (shift + 8)) == pref);
            if (act) atomicAdd(&hist[(k >> shift) & 0xFFu], 1u);
        }
        __syncthreads();
        suf[tid] = hist[tid];
        __syncthreads();
#pragma unroll
        for (int d = 1; d < 256; d <<= 1) {
            unsigned v = (tid + d < 256) ? suf[tid + d] : 0u;
            __syncthreads();
            suf[tid] += v;
            __syncthreads();
        }
        if (suf[tid] >= (unsigned)rem && (tid == 255 || suf[tid + 1] < (unsigned)rem))
            s_selt = tid;
        __syncthreads();
        if (tid == 0) {
            int tt = s_selt;
            unsigned above = (tt == 255) ? 0u : suf[tt + 1];
            s_remaining = rem - (int)above;
            s_prefix = (pref << 8) | (unsigned)tt;
        }
        __syncthreads();
    }

    unsigned T = s_prefix;
    int r = s_remaining;
    if (tid == 0) { s_cntgt = 0; s_cnteq = 0; }
    __syncthreads();
    int* outp = g_idx + rowbase * KK;
    for (int i = tid; i < NN; i += 256) {
        unsigned k = keys[i];
        if (k > T) {
            int pos = atomicAdd(&s_cntgt, 1);
            selK[pos] = k;
            selI[pos] = i;
        } else if (k == T) {
            int pos = atomicAdd(&s_cnteq, 1);
            eq[pos] = i;
        }
    }
    __syncthreads();
    int m = s_cntgt;
    int L = s_cnteq;
    if (tid == 0) {
        for (int a = 1; a < m; ++a) {
            unsigned kk = selK[a]; int ii = selI[a];
            int bp = a - 1;
            while (bp >= 0 && (selK[bp] < kk || (selK[bp] == kk && selI[bp] > ii))) {
                selK[bp + 1] = selK[bp]; selI[bp + 1] = selI[bp]; --bp;
            }
            selK[bp + 1] = kk; selI[bp + 1] = ii;
        }
        for (int a = 0; a < m; ++a) outp[a] = selI[a];
    }
    __syncthreads();
    for (int round = 0; round < r; ++round) {
        int lm = 0x7FFFFFFF;
        for (int i = tid; i < L; i += 256) lm = min(lm, eq[i]);
        rmin[tid] = lm;
        __syncthreads();
#pragma unroll
        for (int s = 128; s > 0; s >>= 1) {
            if (tid < s) rmin[tid] = min(rmin[tid], rmin[tid + s]);
            __syncthreads();
        }
        int mv = rmin[0];
        if (tid == 0) outp[m + round] = mv;
        for (int i = tid; i < L; i += 256)
            if (eq[i] == mv) eq[i] = 0x7FFFFFFF;
        __syncthreads();
    }
}

// ---------------- center GEMM: t[row][o] = sum_c (w[o][C+c]-w[o][c]) * x[row][c] ----------------
__global__ void center_gemm(const float* __restrict__ xin, int use_in, int xoff, int C,
                            const float* __restrict__ w, int O) {
    __shared__ __align__(16) float As[16][68];
    __shared__ __align__(16) float Bs[16][68];
    int r0 = blockIdx.y * 64, o0 = blockIdx.x * 64;
    int tid = threadIdx.x, tx = tid & 15, ty = tid >> 4;
    float acc[4][4] = {};
    int twoC = 2 * C;
    int nch = (C + 15) >> 4;
    for (int ch = 0; ch < nch; ++ch) {
        int c0 = ch * 16;
        for (int t = tid; t < 2048; t += 256) {
            int which = t >> 10;
            int r = (t & 1023) >> 4;
            int cc = t & 15;
            int c = c0 + cc;
            float v = 0.f;
            if (which == 0) {
                if (c < C)
                    v = use_in ? xin[(size_t)(r0 + r) * 3 + c]
                               : g_cat[(size_t)(r0 + r) * CATC + xoff + c];
                As[cc][r] = v;
            } else {
                if (c < C && (o0 + r) < O)
                    v = w[(size_t)(o0 + r) * twoC + C + c] - w[(size_t)(o0 + r) * twoC + c];
                Bs[cc][r] = v;
            }
        }
        __syncthreads();
#pragma unroll
        for (int cc = 0; cc < 16; ++cc) {
            float4 a4 = *(const float4*)&As[cc][ty * 4];
            float4 b4 = *(const float4*)&Bs[cc][tx * 4];
            float aa[4] = {a4.x, a4.y, a4.z, a4.w};
            float bb[4] = {b4.x, b4.y, b4.z, b4.w};
#pragma unroll
            for (int i = 0; i < 4; ++i)
#pragma unroll
                for (int j = 0; j < 4; ++j)
                    acc[i][j] = fmaf(aa[i], bb[j], acc[i][j]);
        }
        __syncthreads();
    }
#pragma unroll
    for (int i = 0; i < 4; ++i) {
        float4 o4 = make_float4(acc[i][0], acc[i][1], acc[i][2], acc[i][3]);
        *(float4*)&g_t[(size_t)(r0 + ty * 4 + i) * O + o0 + tx * 4] = o4;
    }
}

// ---------------- gather GEMM + fused max/sum/sumsq epilogue ----------------
__global__ void gather_gemm(const float* __restrict__ xin, int use_in, int xoff, int C,
                            const float* __restrict__ w, int O, int outoff) {
    __shared__ __align__(16) float As[80][20];
    __shared__ __align__(16) float Bs[16][132];
    __shared__ float redM[16][132];
    __shared__ float redS[16][132];
    __shared__ float redQ[16][132];
    __shared__ int sidx[80];
    int b = blockIdx.z, n0 = blockIdx.y * 4, o0 = blockIdx.x * 128;
    int tid = threadIdx.x, tx = tid & 15, ty = tid >> 4;
    if (tid < 80) sidx[tid] = g_idx[(b * NN + n0 + tid / KK) * KK + tid % KK];
    __syncthreads();
    float acc[5][8] = {};
    int twoC = 2 * C;
    int nch = (C + 15) >> 4;
    for (int ch = 0; ch < nch; ++ch) {
        int c0 = ch * 16;
        for (int t = tid; t < 320; t += 256) {
            int r = t >> 2, seg = t & 3;
            int nbr = sidx[r];
            if (use_in) {
#pragma unroll
                for (int e = 0; e < 4; ++e) {
                    int c = c0 + seg * 4 + e;
                    As[r][seg * 4 + e] = (c < C) ? xin[(size_t)(b * NN + nbr) * 3 + c] : 0.f;
                }
            } else {
                float4 v = *(const float4*)&g_cat[(size_t)(b * NN + nbr) * CATC + xoff + c0 + seg * 4];
                *(float4*)&As[r][seg * 4] = v;
            }
        }
        for (int t = tid; t < 2048; t += 256) {
            int o = t >> 4, cc = t & 15;
            int c = c0 + cc;
            Bs[cc][o] = ((o0 + o) < O && c < C) ? w[(size_t)(o0 + o) * twoC + c] : 0.f;
        }
        __syncthreads();
#pragma unroll
        for (int cc = 0; cc < 16; ++cc) {
            float a0 = As[ty * 5 + 0][cc];
            float a1 = As[ty * 5 + 1][cc];
            float a2 = As[ty * 5 + 2][cc];
            float a3 = As[ty * 5 + 3][cc];
            float a4 = As[ty * 5 + 4][cc];
            float4 b0 = *(const float4*)&Bs[cc][tx * 8];
            float4 b1 = *(const float4*)&Bs[cc][tx * 8 + 4];
            float bb[8] = {b0.x, b0.y, b0.z, b0.w, b1.x, b1.y, b1.z, b1.w};
#pragma unroll
            for (int j = 0; j < 8; ++j) {
                acc[0][j] = fmaf(a0, bb[j], acc[0][j]);
                acc[1][j] = fmaf(a1, bb[j], acc[1][j]);
                acc[2][j] = fmaf(a2, bb[j], acc[2][j]);
                acc[3][j] = fmaf(a3, bb[j], acc[3][j]);
                acc[4][j] = fmaf(a4, bb[j], acc[4][j]);
            }
        }
        __syncthreads();
    }
    int p = ty >> 2;
    int nrow = b * NN + n0 + p;
    float lmax[8], lsum[8], lssq[8];
#pragma unroll
    for (int j = 0; j < 8; ++j) {
        int o = o0 + tx * 8 + j;
        float tval = (o < O) ? g_t[(size_t)nrow * O + o] : 0.f;
        float mx = -3.402823466e38f, s = 0.f, q = 0.f;
#pragma unroll
        for (int i = 0; i < 5; ++i) {
            float h = acc[i][j] + tval;
            mx = fmaxf(mx, h);
            s += h;
            q += h * h;
        }
        lmax[j] = mx; lsum[j] = s; lssq[j] = q;
    }
#pragma unroll
    for (int j = 0; j < 8; ++j) {
        redM[ty][tx * 8 + j] = lmax[j];
        redS[ty][tx * 8 + j] = lsum[j];
        redQ[ty][tx * 8 + j] = lssq[j];
    }
    __syncthreads();
    for (int t = tid; t < 512; t += 256) {
        int pp = t >> 7, col = t & 127;
        float m0 = fmaxf(redM[pp * 4 + 0][col], redM[pp * 4 + 1][col]);
        float m1 = fmaxf(redM[pp * 4 + 2][col], redM[pp * 4 + 3][col]);
        if (o0 + col < O)
            g_cat[(size_t)(b * NN + n0 + pp) * CATC + outoff + o0 + col] = fmaxf(m0, m1);
    }
    if (tid < 128) {
        float s = 0.f, q = 0.f;
#pragma unroll
        for (int yy = 0; yy < 16; ++yy) { s += redS[yy][tid]; q += redQ[yy][tid]; }
        size_t pidx = (((size_t)b * gridDim.x + blockIdx.x) * (NN / 4) + blockIdx.y) * 128 + tid;
        g_partS[pidx] = s;
        g_partQ[pidx] = q;
    }
}

// ---------------- reduce gather partials -> g_sum/g_sumsq ----------------
__global__ void reduce_conv(int O, int oT) {
    int i = blockIdx.x * 256 + threadIdx.x;
    if (i >= BB * O) return;
    int b = i / O, o = i - b * O;
    int ot = o >> 7, col = o & 127;
    float s = 0.f, q = 0.f;
    for (int ny = 0; ny < NN / 4; ++ny) {
        size_t p = (((size_t)b * oT + ot) * (NN / 4) + ny) * 128 + col;
        s += g_partS[p];
        q += g_partQ[p];
    }
    g_sum[i] = s;
    g_sumsq[i] = q;
}

// ---------------- finalize edge conv: instnorm + leaky, in place ----------------
__global__ void finalize_conv(int O, int outoff) {
    int i = blockIdx.x * 256 + threadIdx.x;
    if (i >= BB * NN * O) return;
    int row = i / O;
    int o = i - row * O;
    int b = row >> 11;
    const float cnt = (float)(NN * KK);
    float mean = g_sum[b * O + o] / cnt;
    float var = fmaxf(g_sumsq[b * O + o] / cnt - mean * mean, 0.f);
    float inv = rsqrtf(var + 1e-5f);
    size_t pidx = (size_t)row * CATC + outoff + o;
    float v = (g_cat[pidx] - mean) * inv;
    g_cat[pidx] = v >= 0.f ? v : 0.2f * v;
}

// ---------------- final conv GEMM: 128x128 tile, 8x8 micro ----------------
__global__ void final_gemm(const float* __restrict__ w5) {
    __shared__ __align__(16) float As[16][132];
    __shared__ __align__(16) float Bs[16][132];
    __shared__ float redS[16][128];
    __shared__ float redQ[16][128];
    int r0 = blockIdx.y * 128, o0 = blockIdx.x * 128;
    int tid = threadIdx.x, tx = tid & 15, ty = tid >> 4;
    float acc[8][8] = {};
    for (int ch = 0; ch < 32; ++ch) {
        int c0 = ch * 16;
        for (int q = tid; q < 4096; q += 256) {
            int which = q >> 11;
            int r = (q & 2047) >> 4;
            int cc = q & 15;
            if (which == 0)
                As[cc][r] = g_cat[(size_t)(r0 + r) * CATC + c0 + cc];
            else
                Bs[cc][r] = w5[(size_t)(o0 + r) * 512 + c0 + cc];
        }
        __syncthreads();
#pragma unroll
        for (int cc = 0; cc < 16; ++cc) {
            float4 a0 = *(const float4*)&As[cc][ty * 8];
            float4 a1 = *(const float4*)&As[cc][ty * 8 + 4];
            float4 b0 = *(const float4*)&Bs[cc][tx * 8];
            float4 b1 = *(const float4*)&Bs[cc][tx * 8 + 4];
            float aa[8] = {a0.x, a0.y, a0.z, a0.w, a1.x, a1.y, a1.z, a1.w};
            float bb[8] = {b0.x, b0.y, b0.z, b0.w, b1.x, b1.y, b1.z, b1.w};
#pragma unroll
            for (int i = 0; i < 8; ++i)
#pragma unroll
                for (int j = 0; j < 8; ++j)
                    acc[i][j] = fmaf(aa[i], bb[j], acc[i][j]);
        }
        __syncthreads();
    }
    float ls[8] = {}, lq[8] = {};
#pragma unroll
    for (int i = 0; i < 8; ++i) {
        size_t base = (size_t)(r0 + ty * 8 + i) * 512 + o0 + tx * 8;
        *(float4*)&g_h5[base] = make_float4(acc[i][0], acc[i][1], acc[i][2], acc[i][3]);
        *(float4*)&g_h5[base + 4] = make_float4(acc[i][4], acc[i][5], acc[i][6], acc[i][7]);
#pragma unroll
        for (int j = 0; j < 8; ++j) { ls[j] += acc[i][j]; lq[j] += acc[i][j] * acc[i][j]; }
    }
#pragma unroll
    for (int j = 0; j < 8; ++j) { redS[ty][tx * 8 + j] = ls[j]; redQ[ty][tx * 8 + j] = lq[j]; }
    __syncthreads();
    if (tid < 128) {
        float s = 0.f, q = 0.f;
#pragma unroll
        for (int yy = 0; yy < 16; ++yy) { s += redS[yy][tid]; q += redQ[yy][tid]; }
        size_t p = ((size_t)blockIdx.y * 4 + blockIdx.x) * 128 + tid;
        g_partS[p] = s;
        g_partQ[p] = q;
    }
}

__global__ void reduce_final() {
    int i = blockIdx.x * 256 + threadIdx.x;
    if (i >= BB * 512) return;
    int b = i >> 9, o = i & 511;
    int ox = o >> 7, col = o & 127;
    float s = 0.f, q = 0.f;
    for (int yy = 0; yy < 16; ++yy) {
        size_t p = ((size_t)(b * 16 + yy) * 4 + ox) * 128 + col;
        s += g_partS[p];
        q += g_partQ[p];
    }
    g_sum[i] = s;
    g_sumsq[i] = q;
}

// ---------------- final normalize + leaky + transpose to (B,512,N) ----------------
__global__ void finalize_final(float* __restrict__ out) {
    int n = blockIdx.x * blockDim.x + threadIdx.x;
    int o = blockIdx.y, b = blockIdx.z;
    const float cnt = (float)NN;
    float mean = g_sum[b * 512 + o] / cnt;
    float var = fmaxf(g_sumsq[b * 512 + o] / cnt - mean * mean, 0.f);
    float inv = rsqrtf(var + 1e-5f);
    float v = (g_h5[(size_t)(b * NN + n) * 512 + o] - mean) * inv;
    out[((size_t)b * 512 + o) * NN + n] = v >= 0.f ? v : 0.2f * v;
}

// ---------------- host orchestration ----------------
static void run_edge(const float* xin, int use_in, int xoff, int C,
                     const float* w, int O, int outoff) {
    xx_kernel<<<(BB * NN + 255) / 256, 256>>>(xin, use_in, xoff, C);
    dist_gemm<<<dim3(136, 1, BB), 256>>>(xin, use_in, xoff, C);
    topk_kernel<<<dim3(NN, BB), 256>>>();
    center_gemm<<<dim3((O + 63) / 64, (BB * NN) / 64), 256>>>(xin, use_in, xoff, C, w, O);
    int oT = (O + 127) / 128;
    gather_gemm<<<dim3(oT, NN / 4, BB), 256>>>(xin, use_in, xoff, C, w, O, outoff);
    reduce_conv<<<(BB * O + 255) / 256, 256>>>(O, oT);
    finalize_conv<<<(BB * NN * O + 255) / 256, 256>>>(O, outoff);
}

extern "C" void kernel_launch(void* const* d_in, const int* in_sizes, int n_in,
                              void* d_out, int out_size) {
    const float* x  = (const float*)d_in[0];
    const float* w1 = (const float*)d_in[1];
    const float* w2 = (const float*)d_in[2];
    const float* w3 = (const float*)d_in[3];
    const float* w4 = (const float*)d_in[4];
    const float* w5 = (const float*)d_in[5];
    float* out = (float*)d_out;

    run_edge(x, 1, 0,   3,   w1, 64,  0);    // x1 -> cat[:, :,   0: 64]
    run_edge(x, 0, 0,   64,  w2, 64,  64);   // x2 -> cat[:, :,  64:128]
    run_edge(x, 0, 64,  64,  w3, 128, 128);  // x3 -> cat[:, :, 128:256]
    run_edge(x, 0, 128, 128, w4, 256, 256);  // x4 -> cat[:, :, 256:512]

    final_gemm<<<dim3(512 / 128, (BB * NN) / 128), 256>>>(w5);
    reduce_final<<<(BB * 512 + 255) / 256, 256>>>();
    finalize_final<<<dim3(NN / 256, 512, BB), 256>>>(out);
}